// round 11
// baseline (speedup 1.0000x reference)
#include <cuda_runtime.h>
#include <math.h>

#define DEVINL __device__ __forceinline__

static DEVINL float leaky(float v){ return v > 0.f ? v : 0.2f*v; }

// ---- packed f32x2 helpers (Blackwell FFMA2 path) ----
static DEVINL unsigned long long dup2(float x){
  unsigned long long r; asm("mov.b64 %0, {%1, %1};" : "=l"(r) : "f"(x)); return r;
}
static DEVINL void ffma2(unsigned long long &d, unsigned long long a, unsigned long long b){
  asm("fma.rn.f32x2 %0, %1, %2, %0;" : "+l"(d) : "l"(a), "l"(b));
}
static DEVINL float2 unp2(unsigned long long v){
  float2 f; asm("mov.b64 {%0, %1}, %2;" : "=f"(f.x), "=f"(f.y) : "l"(v)); return f;
}

// ---------------- persistent scratch (no runtime allocation) ----------------
__device__ float g_cc [4*128*64];
__device__ float g_bb [512*512];
__device__ float g_k  [512*98304];            // 201 MB kernel-predictor output
__device__ float g_h  [2][4*32768*64];        // ping-pong h
__device__ float g_o1 [4*32768*64];           // dilated-conv output

// ================= fused cond net =================
#define COND_SMEM ((32*80 + 28*64 + 28*64 + 12288)*4)
__global__ void __launch_bounds__(256) k_cond_fused(
    const float* __restrict__ c,
    const float* __restrict__ inp_w, const float* __restrict__ inp_b,
    const float* __restrict__ res_w1, const float* __restrict__ res_b1,
    const float* __restrict__ res_w2, const float* __restrict__ res_b2){
  extern __shared__ float sm[];
  float* sC = sm;
  float* sA = sm + 32*80;
  float* sB = sA + 28*64;
  float* sW = sB + 28*64;
  int b = blockIdx.y, p0 = blockIdx.x*16;
  int tid = threadIdx.x;
  int o = tid & 63, q = tid >> 6;

  #pragma unroll 1
  for (int idx=tid; idx<32*80; idx+=256){
    int cr = idx/80, ch = idx - cr*80;
    int g = p0 - 8 + cr;
    sC[idx] = (g>=0 && g<128) ? c[((size_t)b*128+g)*80 + ch] : 0.f;
  }
  __syncthreads();

  {
    float acc[7];
    #pragma unroll
    for (int k=0;k<7;k++) acc[k] = inp_b[o];
    #pragma unroll 1
    for (int t=0;t<5;t++){
      #pragma unroll 1
      for (int i=0;i<80;i++){
        float w = inp_w[(t*80+i)*64 + o];
        #pragma unroll
        for (int k=0;k<7;k++){
          int r = -6 + q*7 + k;
          acc[k] += sC[(r+t+6)*80 + i] * w;
        }
      }
    }
    #pragma unroll
    for (int k=0;k<7;k++){
      int r = -6 + q*7 + k;
      int g = p0 + r;
      sA[(r+6)*64 + o] = (g>=0 && g<128) ? leaky(acc[k]) : 0.f;
    }
  }

  #pragma unroll 1
  for (int s=0; s<6; s++){
    int j = s>>1, half = s&1;
    const float* w  = half ? (res_w2 + (size_t)j*3*64*64) : (res_w1 + (size_t)j*3*64*64);
    const float* bi = half ? (res_b2 + j*64) : (res_b1 + j*64);
    __syncthreads();
    #pragma unroll 1
    for (int idx=tid; idx<12288; idx+=256) sW[idx] = w[idx];
    __syncthreads();
    const float* src = half ? sB : sA;
    int lo = s-5, hi = 21-s;
    float acc[7];
    int rr[7];
    #pragma unroll
    for (int k=0;k<7;k++){ acc[k] = bi[o]; rr[k] = lo + q*7 + k; }
    #pragma unroll 1
    for (int t=0;t<3;t++){
      #pragma unroll 1
      for (int i=0;i<64;i++){
        float wv = sW[(t*64+i)*64 + o];
        #pragma unroll
        for (int k=0;k<7;k++){
          int r = rr[k];
          if (r < hi) acc[k] += src[(r+t+5)*64 + i] * wv;
        }
      }
    }
    #pragma unroll
    for (int k=0;k<7;k++){
      int r = rr[k];
      if (r < hi){
        int g = p0 + r;
        if (half){
          if (g>=0 && g<128) sA[(r+6)*64+o] += leaky(acc[k]);
        } else {
          sB[(r+6)*64+o] = (g>=0 && g<128) ? leaky(acc[k]) : 0.f;
        }
      }
    }
  }
  __syncthreads();

  #pragma unroll 1
  for (int idx=tid; idx<16*64; idx+=256){
    int r = idx>>6, oo = idx&63;
    g_cc[((size_t)b*128 + p0 + r)*64 + oo] = sA[(r+6)*64 + oo];
  }
}

// ================= conv_transpose (k=16, s=8, pad (11,11)) — FFMA2 =================
#define CT_SMEM ((2176 + 8192)*4)
__global__ void __launch_bounds__(256) k_convt(const float* __restrict__ x,
                                               const float* __restrict__ ctw,
                                               const float* __restrict__ ctb){
  extern __shared__ float sm[];
  float* lxS = sm;          // 33 rows x pitch 65
  float* wS  = sm + 2176;   // 16 taps x 8 i x 64 o (chunk)
  int b = blockIdx.y, m0 = blockIdx.x*32;
  int tid = threadIdx.x;
  const float* xb = x + (size_t)b*4096*64;
  #pragma unroll 1
  for (int idx=tid; idx<33*64; idx+=256){
    int rr=idx>>6, i=idx&63; int m=m0+rr;
    lxS[rr*65+i] = (m<4096) ? leaky(xb[(size_t)m*64+i]) : 0.f;
  }
  int ts=tid&31, to=tid>>5;
  unsigned long long acc2[4][8];
  #pragma unroll
  for (int mm=0;mm<4;mm++)
    #pragma unroll
    for (int j=0;j<8;j++) acc2[mm][j]=0ULL;

  for (int ch=0; ch<8; ch++){
    __syncthreads();
    #pragma unroll 1
    for (int idx=tid; idx<8192; idx+=256){
      int tap = idx>>9; int rem = idx&511; int ii=rem>>6; int o=rem&63;
      wS[idx] = ctw[(size_t)tap*4096 + (ch*8+ii)*64 + o];
    }
    __syncthreads();
    #pragma unroll
    for (int ii=0;ii<8;ii++){
      unsigned long long lxd[5];
      #pragma unroll
      for (int r=0;r<5;r++) lxd[r] = dup2(lxS[(to*4+r)*65 + (ch*8+ii)]);
      #pragma unroll
      for (int tap=0;tap<8;tap++){
        unsigned long long w2 = *(const unsigned long long*)(wS + tap*512 + ii*64 + 2*ts);
        int j = 7-tap;
        #pragma unroll
        for (int mm=0;mm<4;mm++) ffma2(acc2[mm][j], lxd[mm], w2);
      }
      #pragma unroll
      for (int tap=8;tap<16;tap++){
        unsigned long long w2 = *(const unsigned long long*)(wS + tap*512 + ii*64 + 2*ts);
        int j = 15-tap;
        #pragma unroll
        for (int mm=0;mm<4;mm++) ffma2(acc2[mm][j], lxd[mm+1], w2);
      }
    }
  }
  float c0 = ctb[2*ts], c1 = ctb[2*ts+1];
  float* hb = g_h[0] + (size_t)b*32768*64;
  #pragma unroll
  for (int mm=0;mm<4;mm++)
    #pragma unroll
    for (int j=0;j<8;j++){
      int n = 8*(m0+to*4+mm)+4+j;
      if (n < 32768){
        float2 p = unp2(acc2[mm][j]);
        float2 v; v.x = p.x+c0; v.y = p.y+c1;
        *(float2*)(hb + (size_t)n*64 + 2*ts) = v;
      }
    }
}

// n = 0..3: single tap 11-n from x[0]
__global__ void k_convt_edge(const float* __restrict__ x, const float* __restrict__ ctw,
                             const float* __restrict__ ctb){
  int b = blockIdx.x; int n = threadIdx.x>>6, o = threadIdx.x&63;
  const float* xb = x + (size_t)b*4096*64;
  float acc = ctb[o];
  int tap = 11-n;
  #pragma unroll 8
  for (int i=0;i<64;i++) acc += leaky(xb[i]) * ctw[(size_t)tap*4096 + i*64 + o];
  g_h[0][((size_t)b*32768+n)*64+o] = acc;
}

// ========= kernel-predictor GEMM [512 x 98304] — W-resident, FFMA2, 512 threads =========
// grid: 768 CTAs (n-tiles). Ws[192][128] resident; loop 4 m-tiles; thread tile 4m x 8n.
#define GEMM_SMEM ((24576 + 24576 + 128)*4)
__global__ void __launch_bounds__(512) k_gemm(const float* __restrict__ W,
                                              const float* __restrict__ wb){
  extern __shared__ float smg[];
  float* Ws = smg;            // [k=192][n=128]
  float* As = smg + 24576;    // [k=192][m=128]
  float* biasS = As + 24576;  // [128]
  int tid = threadIdx.x;
  int n0 = blockIdx.x*128;

  // load W slice once (coalesced float4 rows)
  #pragma unroll 1
  for (int idx=tid; idx<6144; idx+=512){
    int k = idx>>5, c4 = (idx&31)*4;
    *(float4*)(Ws + k*128 + c4) = *(const float4*)(W + (size_t)k*98304 + n0 + c4);
  }
  if (tid < 128) biasS[tid] = wb[n0 + tid];

  int tn = tid&15, tm = tid>>4;      // tm in [0,32)
  float bb0[8];

  #pragma unroll 1
  for (int mt=0; mt<4; mt++){          // m-tile == batch index
    __syncthreads();
    #pragma unroll 1
    for (int idx=tid; idx<24576; idx+=512){
      int k = idx>>7, mm_ = idx&127;
      int t = k>>6, ic = k&63, ls = mm_-1+t;
      As[idx] = (ls>=0 && ls<128) ? g_cc[((mt<<7)+ls)*64+ic] : 0.f;
    }
    __syncthreads();
    if (mt == 0){
      #pragma unroll
      for (int q=0;q<4;q++){ bb0[q] = biasS[tn*4+q]; bb0[q+4] = biasS[64+tn*4+q]; }
    }

    unsigned long long acc2[4][4];
    #pragma unroll
    for (int r=0;r<4;r++)
      #pragma unroll
      for (int q=0;q<4;q++) acc2[r][q]=0ULL;

    #pragma unroll 4
    for (int k=0; k<192; k++){
      float4 a = *(const float4*)(As + k*128 + tm*4);
      ulonglong2 bA = *(const ulonglong2*)(Ws + k*128 + tn*4);
      ulonglong2 bB = *(const ulonglong2*)(Ws + k*128 + 64 + tn*4);
      unsigned long long ad[4];
      ad[0]=dup2(a.x); ad[1]=dup2(a.y); ad[2]=dup2(a.z); ad[3]=dup2(a.w);
      #pragma unroll
      for (int r=0;r<4;r++){
        ffma2(acc2[r][0], ad[r], bA.x);
        ffma2(acc2[r][1], ad[r], bA.y);
        ffma2(acc2[r][2], ad[r], bB.x);
        ffma2(acc2[r][3], ad[r], bB.y);
      }
    }

    int c1 = n0 + tn*4, c2 = n0 + 64 + tn*4;
    #pragma unroll
    for (int r=0;r<4;r++){
      int mrow = mt*128 + tm*4 + r;
      size_t row = (size_t)mrow*98304;
      float2 p0 = unp2(acc2[r][0]), p1 = unp2(acc2[r][1]);
      float2 p2 = unp2(acc2[r][2]), p3 = unp2(acc2[r][3]);
      float4 v1, v2;
      v1.x=p0.x+bb0[0]; v1.y=p0.y+bb0[1]; v1.z=p1.x+bb0[2]; v1.w=p1.y+bb0[3];
      v2.x=p2.x+bb0[4]; v2.y=p2.y+bb0[5]; v2.z=p3.x+bb0[6]; v2.w=p3.y+bb0[7];
      *(float4*)(g_k + row + c1) = v1;
      *(float4*)(g_k + row + c2) = v2;
    }
  }
}

// ================= bias-predictor GEMM: [512 x 512] =================
__global__ void k_gemm_b(const float* __restrict__ W, const float* __restrict__ wb){
  int mrow = blockIdx.x;
  int b = mrow>>7, l = mrow&127;
  int n = threadIdx.x*4;
  float4 acc; acc.x=wb[n]; acc.y=wb[n+1]; acc.z=wb[n+2]; acc.w=wb[n+3];
  #pragma unroll
  for (int t=0;t<3;t++){
    int ls = l-1+t; if (ls<0||ls>=128) continue;
    const float* cr = g_cc + ((b<<7)+ls)*64;
    #pragma unroll 4
    for (int i=0;i<64;i++){
      float v = cr[i];
      float4 wv = *(const float4*)(W + (size_t)(t*64+i)*512 + n);
      acc.x += v*wv.x; acc.y += v*wv.y; acc.z += v*wv.z; acc.w += v*wv.w;
    }
  }
  *(float4*)(g_bb + mrow*512 + n) = acc;
}

// ================= dilated conv (k=3, 64->64), input leaky(h) =================
#define DC_SMEM ((12288 + (128+2*27)*65 + 16)*4)
__global__ void __launch_bounds__(256) k_dilconv(int layer, int parity, int d,
                                                 const float* __restrict__ cw,
                                                 const float* __restrict__ cb){
  extern __shared__ float sm[];
  float* wS = sm;            // [t][i][o] 12288
  float* hS = sm + 12288;    // (128+2d) rows x pitch 65
  int b = blockIdx.y, n0 = blockIdx.x*128;
  int tid = threadIdx.x;
  const float* hb = g_h[parity] + (size_t)b*32768*64;
  const float* cwl = cw + (size_t)layer*3*64*64;
  #pragma unroll 1
  for (int idx=tid; idx<12288; idx+=256) wS[idx] = cwl[idx];
  int nrows = 128 + 2*d;
  #pragma unroll 1
  for (int idx=tid; idx<nrows*64; idx+=256){
    int rr=idx>>6, i=idx&63;
    int g = n0 - d + rr;
    hS[rr*65+i] = (g>=0 && g<32768) ? leaky(hb[(size_t)g*64+i]) : 0.f;
  }
  __syncthreads();
  int gch = tid&15, rg = tid>>4;
  int o4 = gch*4;
  int r0 = rg*8;
  float acc[4][8];
  #pragma unroll
  for (int cc2=0;cc2<4;cc2++)
    #pragma unroll
    for (int mm=0;mm<8;mm++) acc[cc2][mm]=0.f;
  #pragma unroll 1
  for (int i=0;i<64;i++){
    #pragma unroll
    for (int t=0;t<3;t++){
      float4 w = *(const float4*)(wS + t*4096 + i*64 + o4);
      const float* hrow = hS + (r0 + t*d)*65 + i;
      #pragma unroll
      for (int mm=0;mm<8;mm++){
        float a = hrow[mm*65];
        acc[0][mm] += a*w.x; acc[1][mm] += a*w.y;
        acc[2][mm] += a*w.z; acc[3][mm] += a*w.w;
      }
    }
  }
  float c0 = cb[layer*64 + o4], c1 = cb[layer*64 + o4+1];
  float c2 = cb[layer*64 + o4+2], c3 = cb[layer*64 + o4+3];
  float* ob = g_o1 + ((size_t)b*32768 + n0)*64;
  #pragma unroll
  for (int mm=0;mm<8;mm++){
    float4 v;
    v.x = leaky(acc[0][mm]+c0); v.y = leaky(acc[1][mm]+c1);
    v.z = leaky(acc[2][mm]+c2); v.w = leaky(acc[3][mm]+c3);
    *(float4*)(ob + (size_t)(r0+mm)*64 + o4) = v;
  }
}

// ================= LVC + gated residual — FFMA2, interleaved weight pairs =========
#define LVC_SMEM ((16960 + 24576 + 128)*4)
__global__ void __launch_bounds__(512,1) k_lvc(int layer, int parity, int is_last,
                                               float* __restrict__ dout){
  extern __shared__ float sm[];
  float* seg = sm;                 // [i=64][pitch 265], m in [0,258)
  float* Ws  = sm + 16960;         // [k=192][64][2]
  float* bS  = sm + 16960 + 24576; // [128]
  int b = blockIdx.y, L = blockIdx.x;
  int tid = threadIdx.x;

  const float* o1b = g_o1 + (size_t)b*32768*64;
  int t0 = L*256 - 1;
  #pragma unroll 1
  for (int idx=tid; idx<258*64; idx+=512){
    int m = idx>>6, i = idx&63;
    int t = t0 + m;
    seg[i*265 + m] = (t>=0 && t<32768) ? o1b[(size_t)t*64 + i] : 0.f;
  }
  int la = layer*128 + L;
  int l = la>>2, q = la&3;
  const float* kb = g_k + (size_t)(b*128+l)*98304 + q*24576;
  #pragma unroll 1
  for (int idx=tid; idx<24576; idx+=512){
    int i = idx/384; int rem = idx - i*384; int o = rem/3; int kk = rem - o*3;
    Ws[((i*3+kk)*64 + (o&63))*2 + (o>>6)] = kb[idx];
  }
  if (tid < 128) bS[tid] = g_bb[(b*128+l)*512 + q*128 + tid];
  __syncthreads();

  int ts = tid&31, to = tid>>5;   // to in [0,16)
  const float* hin = g_h[parity];
  float* hout = is_last ? dout : g_h[parity^1];
  size_t nbase = (size_t)b*32768 + (size_t)L*256;
  float b0 = bS[ts], b1 = bS[ts+64], b2 = bS[ts+32], b3 = bS[ts+96];

  #pragma unroll 1
  for (int ph=0; ph<2; ph++){
    int sbase = to*16 + ph*8;
    int mmidx[8][3];
    #pragma unroll
    for (int ss=0;ss<8;ss++)
      #pragma unroll
      for (int kk=0;kk<3;kk++){
        int pos = 3*(sbase+ss) + kk - 255;
        if (pos < 0) pos = -pos;
        else if (pos > 257) pos = 514 - pos;
        mmidx[ss][kk] = pos;
      }
    unsigned long long ac01[8], ac23[8];
    #pragma unroll
    for (int ss=0;ss<8;ss++){ ac01[ss]=0ULL; ac23[ss]=0ULL; }
    for (int i=0;i<64;i++){
      const float* segr = seg + i*265;
      #pragma unroll
      for (int kk=0;kk<3;kk++){
        const float* wr = Ws + (i*3+kk)*128;
        unsigned long long w01 = *(const unsigned long long*)(wr + 2*ts);
        unsigned long long w23 = *(const unsigned long long*)(wr + 2*ts + 64);
        #pragma unroll
        for (int ss=0;ss<8;ss++){
          unsigned long long ad = dup2(segr[mmidx[ss][kk]]);
          ffma2(ac01[ss], ad, w01);
          ffma2(ac23[ss], ad, w23);
        }
      }
    }
    #pragma unroll
    for (int ss=0;ss<8;ss++){
      size_t gi = (nbase + sbase + ss)*64;
      float2 p01 = unp2(ac01[ss]);
      float s0 = p01.x+b0, t1 = p01.y+b1;
      float g0 = (1.f/(1.f+__expf(-s0))) * tanhf(t1);
      hout[gi+ts] = hin[gi+ts] + g0;
      float2 p23 = unp2(ac23[ss]);
      float s2 = p23.x+b2, t3 = p23.y+b3;
      float g1 = (1.f/(1.f+__expf(-s2))) * tanhf(t3);
      hout[gi+ts+32] = hin[gi+ts+32] + g1;
    }
  }
}

// ================= launch =================
extern "C" void kernel_launch(void* const* d_in, const int* in_sizes, int n_in,
                              void* d_out, int out_size){
  const float* x      = (const float*)d_in[0];
  const float* c      = (const float*)d_in[1];
  const float* ct_w   = (const float*)d_in[2];
  const float* ct_b   = (const float*)d_in[3];
  const float* conv_w = (const float*)d_in[4];
  const float* conv_b = (const float*)d_in[5];
  const float* inp_w  = (const float*)d_in[6];
  const float* inp_b  = (const float*)d_in[7];
  const float* res_w1 = (const float*)d_in[8];
  const float* res_b1 = (const float*)d_in[9];
  const float* res_w2 = (const float*)d_in[10];
  const float* res_b2 = (const float*)d_in[11];
  const float* kern_w = (const float*)d_in[12];
  const float* kern_b = (const float*)d_in[13];
  const float* bias_w = (const float*)d_in[14];
  const float* bias_b = (const float*)d_in[15];
  float* out = (float*)d_out;

  cudaFuncSetAttribute(k_cond_fused, cudaFuncAttributeMaxDynamicSharedMemorySize, COND_SMEM);
  cudaFuncSetAttribute(k_gemm,    cudaFuncAttributeMaxDynamicSharedMemorySize, GEMM_SMEM);
  cudaFuncSetAttribute(k_dilconv, cudaFuncAttributeMaxDynamicSharedMemorySize, DC_SMEM);
  cudaFuncSetAttribute(k_lvc,     cudaFuncAttributeMaxDynamicSharedMemorySize, LVC_SMEM);
  cudaFuncSetAttribute(k_convt,   cudaFuncAttributeMaxDynamicSharedMemorySize, CT_SMEM);

  // 1: cond net -> g_cc
  k_cond_fused<<<dim3(8,4), 256, COND_SMEM>>>(c, inp_w, inp_b, res_w1, res_b1, res_w2, res_b2);
  // 2,3: conv_transpose -> g_h[0]
  k_convt<<<dim3(128,4), 256, CT_SMEM>>>(x, ct_w, ct_b);
  k_convt_edge<<<4, 256>>>(x, ct_w, ct_b);
  // 4: kernel predictor GEMM  (<- 4th launch: ncu captures this)
  k_gemm<<<768, 512, GEMM_SMEM>>>(kern_w, kern_b);
  // 5: bias predictor
  k_gemm_b<<<512, 128>>>(bias_w, bias_b);
  // 6+: 4 LVC layers
  const int dil[4] = {1,3,9,27};
  for (int a=0;a<4;a++){
    int parity = a & 1;
    k_dilconv<<<dim3(256,4), 256, DC_SMEM>>>(a, parity, dil[a], conv_w, conv_b);
    k_lvc<<<dim3(128,4), 512, LVC_SMEM>>>(a, parity, (a==3)?1:0, out);
  }
  (void)in_sizes; (void)n_in; (void)out_size;
}

// round 12
// speedup vs baseline: 1.5015x; 1.5015x over previous
#include <cuda_runtime.h>
#include <math.h>

#define DEVINL __device__ __forceinline__

static DEVINL float leaky(float v){ return v > 0.f ? v : 0.2f*v; }

// ---- packed f32x2 helpers (Blackwell FFMA2 path) ----
static DEVINL unsigned long long dup2(float x){
  unsigned long long r; asm("mov.b64 %0, {%1, %1};" : "=l"(r) : "f"(x)); return r;
}
static DEVINL void ffma2(unsigned long long &d, unsigned long long a, unsigned long long b){
  asm("fma.rn.f32x2 %0, %1, %2, %0;" : "+l"(d) : "l"(a), "l"(b));
}
static DEVINL float2 unp2(unsigned long long v){
  float2 f; asm("mov.b64 {%0, %1}, %2;" : "=f"(f.x), "=f"(f.y) : "l"(v)); return f;
}

// ---------------- persistent scratch (no runtime allocation) ----------------
__device__ float g_cc [4*128*64];
__device__ float g_bb [512*512];
__device__ float g_k  [512*98304];            // 201 MB kernel-predictor output
__device__ float g_h  [2][4*32768*64];        // ping-pong h
__device__ float g_o1 [4*32768*64];           // dilated-conv output

// ================= fused cond net =================
#define COND_SMEM ((32*80 + 28*64 + 28*64 + 12288)*4)
__global__ void __launch_bounds__(256) k_cond_fused(
    const float* __restrict__ c,
    const float* __restrict__ inp_w, const float* __restrict__ inp_b,
    const float* __restrict__ res_w1, const float* __restrict__ res_b1,
    const float* __restrict__ res_w2, const float* __restrict__ res_b2){
  extern __shared__ float sm[];
  float* sC = sm;
  float* sA = sm + 32*80;
  float* sB = sA + 28*64;
  float* sW = sB + 28*64;
  int b = blockIdx.y, p0 = blockIdx.x*16;
  int tid = threadIdx.x;
  int o = tid & 63, q = tid >> 6;

  #pragma unroll 1
  for (int idx=tid; idx<32*80; idx+=256){
    int cr = idx/80, ch = idx - cr*80;
    int g = p0 - 8 + cr;
    sC[idx] = (g>=0 && g<128) ? c[((size_t)b*128+g)*80 + ch] : 0.f;
  }
  __syncthreads();

  {
    float acc[7];
    #pragma unroll
    for (int k=0;k<7;k++) acc[k] = inp_b[o];
    #pragma unroll 1
    for (int t=0;t<5;t++){
      #pragma unroll 1
      for (int i=0;i<80;i++){
        float w = inp_w[(t*80+i)*64 + o];
        #pragma unroll
        for (int k=0;k<7;k++){
          int r = -6 + q*7 + k;
          acc[k] += sC[(r+t+6)*80 + i] * w;
        }
      }
    }
    #pragma unroll
    for (int k=0;k<7;k++){
      int r = -6 + q*7 + k;
      int g = p0 + r;
      sA[(r+6)*64 + o] = (g>=0 && g<128) ? leaky(acc[k]) : 0.f;
    }
  }

  #pragma unroll 1
  for (int s=0; s<6; s++){
    int j = s>>1, half = s&1;
    const float* w  = half ? (res_w2 + (size_t)j*3*64*64) : (res_w1 + (size_t)j*3*64*64);
    const float* bi = half ? (res_b2 + j*64) : (res_b1 + j*64);
    __syncthreads();
    #pragma unroll 1
    for (int idx=tid; idx<12288; idx+=256) sW[idx] = w[idx];
    __syncthreads();
    const float* src = half ? sB : sA;
    int lo = s-5, hi = 21-s;
    float acc[7];
    int rr[7];
    #pragma unroll
    for (int k=0;k<7;k++){ acc[k] = bi[o]; rr[k] = lo + q*7 + k; }
    #pragma unroll 1
    for (int t=0;t<3;t++){
      #pragma unroll 1
      for (int i=0;i<64;i++){
        float wv = sW[(t*64+i)*64 + o];
        #pragma unroll
        for (int k=0;k<7;k++){
          int r = rr[k];
          if (r < hi) acc[k] += src[(r+t+5)*64 + i] * wv;
        }
      }
    }
    #pragma unroll
    for (int k=0;k<7;k++){
      int r = rr[k];
      if (r < hi){
        int g = p0 + r;
        if (half){
          if (g>=0 && g<128) sA[(r+6)*64+o] += leaky(acc[k]);
        } else {
          sB[(r+6)*64+o] = (g>=0 && g<128) ? leaky(acc[k]) : 0.f;
        }
      }
    }
  }
  __syncthreads();

  #pragma unroll 1
  for (int idx=tid; idx<16*64; idx+=256){
    int r = idx>>6, oo = idx&63;
    g_cc[((size_t)b*128 + p0 + r)*64 + oo] = sA[(r+6)*64 + oo];
  }
}

// ================= conv_transpose (k=16, s=8, pad (11,11)) — FFMA2 =================
#define CT_SMEM ((2176 + 8192)*4)
__global__ void __launch_bounds__(256) k_convt(const float* __restrict__ x,
                                               const float* __restrict__ ctw,
                                               const float* __restrict__ ctb){
  extern __shared__ float sm[];
  float* lxS = sm;          // 33 rows x pitch 65
  float* wS  = sm + 2176;   // 16 taps x 8 i x 64 o (chunk)
  int b = blockIdx.y, m0 = blockIdx.x*32;
  int tid = threadIdx.x;
  const float* xb = x + (size_t)b*4096*64;
  #pragma unroll 1
  for (int idx=tid; idx<33*64; idx+=256){
    int rr=idx>>6, i=idx&63; int m=m0+rr;
    lxS[rr*65+i] = (m<4096) ? leaky(xb[(size_t)m*64+i]) : 0.f;
  }
  int ts=tid&31, to=tid>>5;
  unsigned long long acc2[4][8];
  #pragma unroll
  for (int mm=0;mm<4;mm++)
    #pragma unroll
    for (int j=0;j<8;j++) acc2[mm][j]=0ULL;

  for (int ch=0; ch<8; ch++){
    __syncthreads();
    #pragma unroll 1
    for (int idx=tid; idx<8192; idx+=256){
      int tap = idx>>9; int rem = idx&511; int ii=rem>>6; int o=rem&63;
      wS[idx] = ctw[(size_t)tap*4096 + (ch*8+ii)*64 + o];
    }
    __syncthreads();
    #pragma unroll
    for (int ii=0;ii<8;ii++){
      unsigned long long lxd[5];
      #pragma unroll
      for (int r=0;r<5;r++) lxd[r] = dup2(lxS[(to*4+r)*65 + (ch*8+ii)]);
      #pragma unroll
      for (int tap=0;tap<8;tap++){
        unsigned long long w2 = *(const unsigned long long*)(wS + tap*512 + ii*64 + 2*ts);
        int j = 7-tap;
        #pragma unroll
        for (int mm=0;mm<4;mm++) ffma2(acc2[mm][j], lxd[mm], w2);
      }
      #pragma unroll
      for (int tap=8;tap<16;tap++){
        unsigned long long w2 = *(const unsigned long long*)(wS + tap*512 + ii*64 + 2*ts);
        int j = 15-tap;
        #pragma unroll
        for (int mm=0;mm<4;mm++) ffma2(acc2[mm][j], lxd[mm+1], w2);
      }
    }
  }
  float c0 = ctb[2*ts], c1 = ctb[2*ts+1];
  float* hb = g_h[0] + (size_t)b*32768*64;
  #pragma unroll
  for (int mm=0;mm<4;mm++)
    #pragma unroll
    for (int j=0;j<8;j++){
      int n = 8*(m0+to*4+mm)+4+j;
      if (n < 32768){
        float2 p = unp2(acc2[mm][j]);
        float2 v; v.x = p.x+c0; v.y = p.y+c1;
        *(float2*)(hb + (size_t)n*64 + 2*ts) = v;
      }
    }
}

// n = 0..3: single tap 11-n from x[0]
__global__ void k_convt_edge(const float* __restrict__ x, const float* __restrict__ ctw,
                             const float* __restrict__ ctb){
  int b = blockIdx.x; int n = threadIdx.x>>6, o = threadIdx.x&63;
  const float* xb = x + (size_t)b*4096*64;
  float acc = ctb[o];
  int tap = 11-n;
  #pragma unroll 8
  for (int i=0;i<64;i++) acc += leaky(xb[i]) * ctw[(size_t)tap*4096 + i*64 + o];
  g_h[0][((size_t)b*32768+n)*64+o] = acc;
}

// ========= kernel-predictor GEMM [512 x 98304] — FFMA2 (proven R9 version) =========
#define GEMM_SMEM ((12288 + 2048)*4)
__global__ void __launch_bounds__(256) k_gemm(const float* __restrict__ W,
                                              const float* __restrict__ wb){
  extern __shared__ float smg[];
  float* As = smg;          // [k=192][m=64]
  float* Bs = smg + 12288;  // 2 x [8][128]
  int tid = threadIdx.x;
  int n0 = blockIdx.x*128, m0 = blockIdx.y*64;
  #pragma unroll 1
  for (int it=0; it<48; it++){
    int idx = tid + it*256;
    int k = idx>>6, mm_ = idx&63;
    int mg = m0+mm_; int b2 = mg>>7, l = mg&127;
    int t = k>>6, ic = k&63, ls = l-1+t;
    As[idx] = (ls>=0 && ls<128) ? g_cc[((b2<<7)+ls)*64+ic] : 0.f;
  }
  int brow = tid>>5, bcol = (tid&31)*4;
  *(float4*)(Bs + brow*128 + bcol) = *(const float4*)(W + (size_t)brow*98304 + n0 + bcol);
  __syncthreads();
  int tn = tid&15, tm = tid>>4;
  unsigned long long acc2[4][4];
  #pragma unroll
  for (int r=0;r<4;r++)
    #pragma unroll
    for (int q=0;q<4;q++) acc2[r][q]=0ULL;
  for (int kc=0; kc<24; kc++){
    float4 nb;
    if (kc<23) nb = *(const float4*)(W + (size_t)((kc+1)*8+brow)*98304 + n0 + bcol);
    const float* Bc = Bs + (kc&1)*1024;
    #pragma unroll
    for (int kk=0; kk<8; kk++){
      int k = kc*8+kk;
      float4 a = *(const float4*)(As + k*64 + tm*4);
      ulonglong2 bA = *(const ulonglong2*)(Bc + kk*128 + tn*4);
      ulonglong2 bB = *(const ulonglong2*)(Bc + kk*128 + 64 + tn*4);
      unsigned long long ad[4];
      ad[0]=dup2(a.x); ad[1]=dup2(a.y); ad[2]=dup2(a.z); ad[3]=dup2(a.w);
      #pragma unroll
      for (int r=0;r<4;r++){
        ffma2(acc2[r][0], ad[r], bA.x);
        ffma2(acc2[r][1], ad[r], bA.y);
        ffma2(acc2[r][2], ad[r], bB.x);
        ffma2(acc2[r][3], ad[r], bB.y);
      }
    }
    __syncthreads();
    if (kc<23) *(float4*)(Bs + ((kc+1)&1)*1024 + brow*128 + bcol) = nb;
    __syncthreads();
  }
  int c1 = n0 + tn*4, c2 = n0 + 64 + tn*4;
  float bb0[8];
  #pragma unroll
  for (int q=0;q<4;q++){ bb0[q] = wb[c1+q]; bb0[q+4] = wb[c2+q]; }
  #pragma unroll
  for (int r=0;r<4;r++){
    size_t row = (size_t)(m0 + tm*4 + r)*98304;
    float2 p0 = unp2(acc2[r][0]), p1 = unp2(acc2[r][1]);
    float2 p2 = unp2(acc2[r][2]), p3 = unp2(acc2[r][3]);
    float4 v1, v2;
    v1.x=p0.x+bb0[0]; v1.y=p0.y+bb0[1]; v1.z=p1.x+bb0[2]; v1.w=p1.y+bb0[3];
    v2.x=p2.x+bb0[4]; v2.y=p2.y+bb0[5]; v2.z=p3.x+bb0[6]; v2.w=p3.y+bb0[7];
    *(float4*)(g_k + row + c1) = v1;
    *(float4*)(g_k + row + c2) = v2;
  }
}

// ================= bias-predictor GEMM: [512 x 512] =================
__global__ void k_gemm_b(const float* __restrict__ W, const float* __restrict__ wb){
  int mrow = blockIdx.x;
  int b = mrow>>7, l = mrow&127;
  int n = threadIdx.x*4;
  float4 acc; acc.x=wb[n]; acc.y=wb[n+1]; acc.z=wb[n+2]; acc.w=wb[n+3];
  #pragma unroll
  for (int t=0;t<3;t++){
    int ls = l-1+t; if (ls<0||ls>=128) continue;
    const float* cr = g_cc + ((b<<7)+ls)*64;
    #pragma unroll 4
    for (int i=0;i<64;i++){
      float v = cr[i];
      float4 wv = *(const float4*)(W + (size_t)(t*64+i)*512 + n);
      acc.x += v*wv.x; acc.y += v*wv.y; acc.z += v*wv.z; acc.w += v*wv.w;
    }
  }
  *(float4*)(g_bb + mrow*512 + n) = acc;
}

// ================= dilated conv (k=3, 64->64) — FFMA2 pairs =================
#define DC_SMEM ((12288 + (128+2*27)*65 + 16)*4)
__global__ void __launch_bounds__(256) k_dilconv(int layer, int parity, int d,
                                                 const float* __restrict__ cw,
                                                 const float* __restrict__ cb){
  extern __shared__ float sm[];
  float* wS = sm;            // [t][i][o] 12288
  float* hS = sm + 12288;    // (128+2d) rows x pitch 65
  int b = blockIdx.y, n0 = blockIdx.x*128;
  int tid = threadIdx.x;
  const float* hb = g_h[parity] + (size_t)b*32768*64;
  const float* cwl = cw + (size_t)layer*3*64*64;
  #pragma unroll 1
  for (int idx=tid; idx<12288; idx+=256) wS[idx] = cwl[idx];
  int nrows = 128 + 2*d;
  #pragma unroll 1
  for (int idx=tid; idx<nrows*64; idx+=256){
    int rr=idx>>6, i=idx&63;
    int g = n0 - d + rr;
    hS[rr*65+i] = (g>=0 && g<32768) ? leaky(hb[(size_t)g*64+i]) : 0.f;
  }
  __syncthreads();
  int gch = tid&15, rg = tid>>4;
  int o4 = gch*4;
  int r0 = rg*8;
  unsigned long long a01[8], a23[8];
  #pragma unroll
  for (int mm=0;mm<8;mm++){ a01[mm]=0ULL; a23[mm]=0ULL; }
  #pragma unroll 1
  for (int i=0;i<64;i++){
    #pragma unroll
    for (int t=0;t<3;t++){
      ulonglong2 w2 = *(const ulonglong2*)(wS + t*4096 + i*64 + o4);
      const float* hrow = hS + (r0 + t*d)*65 + i;
      #pragma unroll
      for (int mm=0;mm<8;mm++){
        unsigned long long ad = dup2(hrow[mm*65]);
        ffma2(a01[mm], ad, w2.x);
        ffma2(a23[mm], ad, w2.y);
      }
    }
  }
  float c0 = cb[layer*64 + o4], c1 = cb[layer*64 + o4+1];
  float c2 = cb[layer*64 + o4+2], c3 = cb[layer*64 + o4+3];
  float* ob = g_o1 + ((size_t)b*32768 + n0)*64;
  #pragma unroll
  for (int mm=0;mm<8;mm++){
    float2 p01 = unp2(a01[mm]), p23 = unp2(a23[mm]);
    float4 v;
    v.x = leaky(p01.x+c0); v.y = leaky(p01.y+c1);
    v.z = leaky(p23.x+c2); v.w = leaky(p23.y+c3);
    *(float4*)(ob + (size_t)(r0+mm)*64 + o4) = v;
  }
}

// ================= LVC + gated residual — FFMA2, interleaved weight pairs =========
#define LVC_SMEM ((16960 + 24576 + 128)*4)
__global__ void __launch_bounds__(512,1) k_lvc(int layer, int parity, int is_last,
                                               float* __restrict__ dout){
  extern __shared__ float sm[];
  float* seg = sm;                 // [i=64][pitch 265], m in [0,258)
  float* Ws  = sm + 16960;         // [k=192][64][2]
  float* bS  = sm + 16960 + 24576; // [128]
  int b = blockIdx.y, L = blockIdx.x;
  int tid = threadIdx.x;

  const float* o1b = g_o1 + (size_t)b*32768*64;
  int t0 = L*256 - 1;
  #pragma unroll 1
  for (int idx=tid; idx<258*64; idx+=512){
    int m = idx>>6, i = idx&63;
    int t = t0 + m;
    seg[i*265 + m] = (t>=0 && t<32768) ? o1b[(size_t)t*64 + i] : 0.f;
  }
  int la = layer*128 + L;
  int l = la>>2, q = la&3;
  const float* kb = g_k + (size_t)(b*128+l)*98304 + q*24576;
  #pragma unroll 1
  for (int idx=tid; idx<24576; idx+=512){
    int i = idx/384; int rem = idx - i*384; int o = rem/3; int kk = rem - o*3;
    Ws[((i*3+kk)*64 + (o&63))*2 + (o>>6)] = kb[idx];
  }
  if (tid < 128) bS[tid] = g_bb[(b*128+l)*512 + q*128 + tid];
  __syncthreads();

  int ts = tid&31, to = tid>>5;   // to in [0,16)
  const float* hin = g_h[parity];
  float* hout = is_last ? dout : g_h[parity^1];
  size_t nbase = (size_t)b*32768 + (size_t)L*256;
  float b0 = bS[ts], b1 = bS[ts+64], b2 = bS[ts+32], b3 = bS[ts+96];

  #pragma unroll 1
  for (int ph=0; ph<2; ph++){
    int sbase = to*16 + ph*8;
    int mmidx[8][3];
    #pragma unroll
    for (int ss=0;ss<8;ss++)
      #pragma unroll
      for (int kk=0;kk<3;kk++){
        int pos = 3*(sbase+ss) + kk - 255;
        if (pos < 0) pos = -pos;
        else if (pos > 257) pos = 514 - pos;
        mmidx[ss][kk] = pos;
      }
    unsigned long long ac01[8], ac23[8];
    #pragma unroll
    for (int ss=0;ss<8;ss++){ ac01[ss]=0ULL; ac23[ss]=0ULL; }
    for (int i=0;i<64;i++){
      const float* segr = seg + i*265;
      #pragma unroll
      for (int kk=0;kk<3;kk++){
        const float* wr = Ws + (i*3+kk)*128;
        unsigned long long w01 = *(const unsigned long long*)(wr + 2*ts);
        unsigned long long w23 = *(const unsigned long long*)(wr + 2*ts + 64);
        #pragma unroll
        for (int ss=0;ss<8;ss++){
          unsigned long long ad = dup2(segr[mmidx[ss][kk]]);
          ffma2(ac01[ss], ad, w01);
          ffma2(ac23[ss], ad, w23);
        }
      }
    }
    #pragma unroll
    for (int ss=0;ss<8;ss++){
      size_t gi = (nbase + sbase + ss)*64;
      float2 p01 = unp2(ac01[ss]);
      float s0 = p01.x+b0, t1 = p01.y+b1;
      float g0 = (1.f/(1.f+__expf(-s0))) * tanhf(t1);
      hout[gi+ts] = hin[gi+ts] + g0;
      float2 p23 = unp2(ac23[ss]);
      float s2 = p23.x+b2, t3 = p23.y+b3;
      float g1 = (1.f/(1.f+__expf(-s2))) * tanhf(t3);
      hout[gi+ts+32] = hin[gi+ts+32] + g1;
    }
  }
}

// ================= launch =================
extern "C" void kernel_launch(void* const* d_in, const int* in_sizes, int n_in,
                              void* d_out, int out_size){
  const float* x      = (const float*)d_in[0];
  const float* c      = (const float*)d_in[1];
  const float* ct_w   = (const float*)d_in[2];
  const float* ct_b   = (const float*)d_in[3];
  const float* conv_w = (const float*)d_in[4];
  const float* conv_b = (const float*)d_in[5];
  const float* inp_w  = (const float*)d_in[6];
  const float* inp_b  = (const float*)d_in[7];
  const float* res_w1 = (const float*)d_in[8];
  const float* res_b1 = (const float*)d_in[9];
  const float* res_w2 = (const float*)d_in[10];
  const float* res_b2 = (const float*)d_in[11];
  const float* kern_w = (const float*)d_in[12];
  const float* kern_b = (const float*)d_in[13];
  const float* bias_w = (const float*)d_in[14];
  const float* bias_b = (const float*)d_in[15];
  float* out = (float*)d_out;

  cudaFuncSetAttribute(k_cond_fused, cudaFuncAttributeMaxDynamicSharedMemorySize, COND_SMEM);
  cudaFuncSetAttribute(k_gemm,    cudaFuncAttributeMaxDynamicSharedMemorySize, GEMM_SMEM);
  cudaFuncSetAttribute(k_dilconv, cudaFuncAttributeMaxDynamicSharedMemorySize, DC_SMEM);
  cudaFuncSetAttribute(k_lvc,     cudaFuncAttributeMaxDynamicSharedMemorySize, LVC_SMEM);
  cudaFuncSetAttribute(k_convt,   cudaFuncAttributeMaxDynamicSharedMemorySize, CT_SMEM);

  // 1: cond net -> g_cc
  k_cond_fused<<<dim3(8,4), 256, COND_SMEM>>>(c, inp_w, inp_b, res_w1, res_b1, res_w2, res_b2);
  // 2,3: conv_transpose -> g_h[0]
  k_convt<<<dim3(128,4), 256, CT_SMEM>>>(x, ct_w, ct_b);
  k_convt_edge<<<4, 256>>>(x, ct_w, ct_b);
  // 4: kernel predictor GEMM  (<- 4th launch: ncu captures this)
  k_gemm<<<dim3(768,8), 256, GEMM_SMEM>>>(kern_w, kern_b);
  // 5: bias predictor
  k_gemm_b<<<512, 128>>>(bias_w, bias_b);
  // 6+: 4 LVC layers
  const int dil[4] = {1,3,9,27};
  for (int a=0;a<4;a++){
    int parity = a & 1;
    k_dilconv<<<dim3(256,4), 256, DC_SMEM>>>(a, parity, dil[a], conv_w, conv_b);
    k_lvc<<<dim3(128,4), 512, LVC_SMEM>>>(a, parity, (a==3)?1:0, out);
  }
  (void)in_sizes; (void)n_in; (void)out_size;
}

// round 13
// speedup vs baseline: 1.9072x; 1.2702x over previous
#include <cuda_runtime.h>
#include <math.h>

#define DEVINL __device__ __forceinline__

static DEVINL float leaky(float v){ return v > 0.f ? v : 0.2f*v; }

// ---- packed f32x2 helpers (Blackwell FFMA2 path) ----
static DEVINL unsigned long long dup2(float x){
  unsigned long long r; asm("mov.b64 %0, {%1, %1};" : "=l"(r) : "f"(x)); return r;
}
static DEVINL void ffma2(unsigned long long &d, unsigned long long a, unsigned long long b){
  asm("fma.rn.f32x2 %0, %1, %2, %0;" : "+l"(d) : "l"(a), "l"(b));
}
static DEVINL float2 unp2(unsigned long long v){
  float2 f; asm("mov.b64 {%0, %1}, %2;" : "=f"(f.x), "=f"(f.y) : "l"(v)); return f;
}

// ---------------- persistent scratch (no runtime allocation) ----------------
__device__ float g_cc [4*128*64];
__device__ float g_bb [512*512];
__device__ float g_k  [512*98304];            // 201 MB kernel-predictor output
__device__ float g_h  [2][4*32768*64];        // ping-pong h
__device__ float g_o1 [4*32768*64];           // dilated-conv output

// ================= fused cond net =================
#define COND_SMEM ((32*80 + 28*64 + 28*64 + 12288)*4)
__global__ void __launch_bounds__(256) k_cond_fused(
    const float* __restrict__ c,
    const float* __restrict__ inp_w, const float* __restrict__ inp_b,
    const float* __restrict__ res_w1, const float* __restrict__ res_b1,
    const float* __restrict__ res_w2, const float* __restrict__ res_b2){
  extern __shared__ float sm[];
  float* sC = sm;
  float* sA = sm + 32*80;
  float* sB = sA + 28*64;
  float* sW = sB + 28*64;
  int b = blockIdx.y, p0 = blockIdx.x*16;
  int tid = threadIdx.x;
  int o = tid & 63, q = tid >> 6;

  #pragma unroll 1
  for (int idx=tid; idx<32*80; idx+=256){
    int cr = idx/80, ch = idx - cr*80;
    int g = p0 - 8 + cr;
    sC[idx] = (g>=0 && g<128) ? c[((size_t)b*128+g)*80 + ch] : 0.f;
  }
  __syncthreads();

  {
    float acc[7];
    #pragma unroll
    for (int k=0;k<7;k++) acc[k] = inp_b[o];
    #pragma unroll 1
    for (int t=0;t<5;t++){
      #pragma unroll 1
      for (int i=0;i<80;i++){
        float w = inp_w[(t*80+i)*64 + o];
        #pragma unroll
        for (int k=0;k<7;k++){
          int r = -6 + q*7 + k;
          acc[k] += sC[(r+t+6)*80 + i] * w;
        }
      }
    }
    #pragma unroll
    for (int k=0;k<7;k++){
      int r = -6 + q*7 + k;
      int g = p0 + r;
      sA[(r+6)*64 + o] = (g>=0 && g<128) ? leaky(acc[k]) : 0.f;
    }
  }

  #pragma unroll 1
  for (int s=0; s<6; s++){
    int j = s>>1, half = s&1;
    const float* w  = half ? (res_w2 + (size_t)j*3*64*64) : (res_w1 + (size_t)j*3*64*64);
    const float* bi = half ? (res_b2 + j*64) : (res_b1 + j*64);
    __syncthreads();
    #pragma unroll 1
    for (int idx=tid; idx<12288; idx+=256) sW[idx] = w[idx];
    __syncthreads();
    const float* src = half ? sB : sA;
    int lo = s-5, hi = 21-s;
    float acc[7];
    int rr[7];
    #pragma unroll
    for (int k=0;k<7;k++){ acc[k] = bi[o]; rr[k] = lo + q*7 + k; }
    #pragma unroll 1
    for (int t=0;t<3;t++){
      #pragma unroll 1
      for (int i=0;i<64;i++){
        float wv = sW[(t*64+i)*64 + o];
        #pragma unroll
        for (int k=0;k<7;k++){
          int r = rr[k];
          if (r < hi) acc[k] += src[(r+t+5)*64 + i] * wv;
        }
      }
    }
    #pragma unroll
    for (int k=0;k<7;k++){
      int r = rr[k];
      if (r < hi){
        int g = p0 + r;
        if (half){
          if (g>=0 && g<128) sA[(r+6)*64+o] += leaky(acc[k]);
        } else {
          sB[(r+6)*64+o] = (g>=0 && g<128) ? leaky(acc[k]) : 0.f;
        }
      }
    }
  }
  __syncthreads();

  #pragma unroll 1
  for (int idx=tid; idx<16*64; idx+=256){
    int r = idx>>6, oo = idx&63;
    g_cc[((size_t)b*128 + p0 + r)*64 + oo] = sA[(r+6)*64 + oo];
  }
}

// ================= conv_transpose (k=16, s=8, pad (11,11)) — FFMA2 =================
#define CT_SMEM ((2176 + 8192)*4)
__global__ void __launch_bounds__(256) k_convt(const float* __restrict__ x,
                                               const float* __restrict__ ctw,
                                               const float* __restrict__ ctb){
  extern __shared__ float sm[];
  float* lxS = sm;          // 33 rows x pitch 65
  float* wS  = sm + 2176;   // 16 taps x 8 i x 64 o (chunk)
  int b = blockIdx.y, m0 = blockIdx.x*32;
  int tid = threadIdx.x;
  const float* xb = x + (size_t)b*4096*64;
  #pragma unroll 1
  for (int idx=tid; idx<33*64; idx+=256){
    int rr=idx>>6, i=idx&63; int m=m0+rr;
    lxS[rr*65+i] = (m<4096) ? leaky(xb[(size_t)m*64+i]) : 0.f;
  }
  int ts=tid&31, to=tid>>5;
  unsigned long long acc2[4][8];
  #pragma unroll
  for (int mm=0;mm<4;mm++)
    #pragma unroll
    for (int j=0;j<8;j++) acc2[mm][j]=0ULL;

  for (int ch=0; ch<8; ch++){
    __syncthreads();
    #pragma unroll 1
    for (int idx=tid; idx<2048; idx+=256){
      int tap = idx>>7; int rem = idx&127; int ii=rem>>4; int o4=(rem&15)*4;
      *(float4*)(wS + tap*512 + ii*64 + o4) =
        *(const float4*)(ctw + (size_t)tap*4096 + (ch*8+ii)*64 + o4);
    }
    __syncthreads();
    #pragma unroll
    for (int ii=0;ii<8;ii++){
      unsigned long long lxd[5];
      #pragma unroll
      for (int r=0;r<5;r++) lxd[r] = dup2(lxS[(to*4+r)*65 + (ch*8+ii)]);
      #pragma unroll
      for (int tap=0;tap<8;tap++){
        unsigned long long w2 = *(const unsigned long long*)(wS + tap*512 + ii*64 + 2*ts);
        int j = 7-tap;
        #pragma unroll
        for (int mm=0;mm<4;mm++) ffma2(acc2[mm][j], lxd[mm], w2);
      }
      #pragma unroll
      for (int tap=8;tap<16;tap++){
        unsigned long long w2 = *(const unsigned long long*)(wS + tap*512 + ii*64 + 2*ts);
        int j = 15-tap;
        #pragma unroll
        for (int mm=0;mm<4;mm++) ffma2(acc2[mm][j], lxd[mm+1], w2);
      }
    }
  }
  float c0 = ctb[2*ts], c1 = ctb[2*ts+1];
  float* hb = g_h[0] + (size_t)b*32768*64;
  #pragma unroll
  for (int mm=0;mm<4;mm++)
    #pragma unroll
    for (int j=0;j<8;j++){
      int n = 8*(m0+to*4+mm)+4+j;
      if (n < 32768){
        float2 p = unp2(acc2[mm][j]);
        float2 v; v.x = p.x+c0; v.y = p.y+c1;
        *(float2*)(hb + (size_t)n*64 + 2*ts) = v;
      }
    }
}

// n = 0..3: single tap 11-n from x[0]
__global__ void k_convt_edge(const float* __restrict__ x, const float* __restrict__ ctw,
                             const float* __restrict__ ctb){
  int b = blockIdx.x; int n = threadIdx.x>>6, o = threadIdx.x&63;
  const float* xb = x + (size_t)b*4096*64;
  float acc = ctb[o];
  int tap = 11-n;
  #pragma unroll 8
  for (int i=0;i<64;i++) acc += leaky(xb[i]) * ctw[(size_t)tap*4096 + i*64 + o];
  g_h[0][((size_t)b*32768+n)*64+o] = acc;
}

// ========= kernel-predictor GEMM [512 x 98304] — FFMA2 (proven R9 version) =========
#define GEMM_SMEM ((12288 + 2048)*4)
__global__ void __launch_bounds__(256) k_gemm(const float* __restrict__ W,
                                              const float* __restrict__ wb){
  extern __shared__ float smg[];
  float* As = smg;          // [k=192][m=64]
  float* Bs = smg + 12288;  // 2 x [8][128]
  int tid = threadIdx.x;
  int n0 = blockIdx.x*128, m0 = blockIdx.y*64;
  #pragma unroll 1
  for (int it=0; it<48; it++){
    int idx = tid + it*256;
    int k = idx>>6, mm_ = idx&63;
    int mg = m0+mm_; int b2 = mg>>7, l = mg&127;
    int t = k>>6, ic = k&63, ls = l-1+t;
    As[idx] = (ls>=0 && ls<128) ? g_cc[((b2<<7)+ls)*64+ic] : 0.f;
  }
  int brow = tid>>5, bcol = (tid&31)*4;
  *(float4*)(Bs + brow*128 + bcol) = *(const float4*)(W + (size_t)brow*98304 + n0 + bcol);
  __syncthreads();
  int tn = tid&15, tm = tid>>4;
  unsigned long long acc2[4][4];
  #pragma unroll
  for (int r=0;r<4;r++)
    #pragma unroll
    for (int q=0;q<4;q++) acc2[r][q]=0ULL;
  for (int kc=0; kc<24; kc++){
    float4 nb;
    if (kc<23) nb = *(const float4*)(W + (size_t)((kc+1)*8+brow)*98304 + n0 + bcol);
    const float* Bc = Bs + (kc&1)*1024;
    #pragma unroll
    for (int kk=0; kk<8; kk++){
      int k = kc*8+kk;
      float4 a = *(const float4*)(As + k*64 + tm*4);
      ulonglong2 bA = *(const ulonglong2*)(Bc + kk*128 + tn*4);
      ulonglong2 bB = *(const ulonglong2*)(Bc + kk*128 + 64 + tn*4);
      unsigned long long ad[4];
      ad[0]=dup2(a.x); ad[1]=dup2(a.y); ad[2]=dup2(a.z); ad[3]=dup2(a.w);
      #pragma unroll
      for (int r=0;r<4;r++){
        ffma2(acc2[r][0], ad[r], bA.x);
        ffma2(acc2[r][1], ad[r], bA.y);
        ffma2(acc2[r][2], ad[r], bB.x);
        ffma2(acc2[r][3], ad[r], bB.y);
      }
    }
    __syncthreads();
    if (kc<23) *(float4*)(Bs + ((kc+1)&1)*1024 + brow*128 + bcol) = nb;
    __syncthreads();
  }
  int c1 = n0 + tn*4, c2 = n0 + 64 + tn*4;
  float bb0[8];
  #pragma unroll
  for (int q=0;q<4;q++){ bb0[q] = wb[c1+q]; bb0[q+4] = wb[c2+q]; }
  #pragma unroll
  for (int r=0;r<4;r++){
    size_t row = (size_t)(m0 + tm*4 + r)*98304;
    float2 p0 = unp2(acc2[r][0]), p1 = unp2(acc2[r][1]);
    float2 p2 = unp2(acc2[r][2]), p3 = unp2(acc2[r][3]);
    float4 v1, v2;
    v1.x=p0.x+bb0[0]; v1.y=p0.y+bb0[1]; v1.z=p1.x+bb0[2]; v1.w=p1.y+bb0[3];
    v2.x=p2.x+bb0[4]; v2.y=p2.y+bb0[5]; v2.z=p3.x+bb0[6]; v2.w=p3.y+bb0[7];
    *(float4*)(g_k + row + c1) = v1;
    *(float4*)(g_k + row + c2) = v2;
  }
}

// ================= bias-predictor GEMM: [512 x 512] =================
__global__ void k_gemm_b(const float* __restrict__ W, const float* __restrict__ wb){
  int mrow = blockIdx.x;
  int b = mrow>>7, l = mrow&127;
  int n = threadIdx.x*4;
  float4 acc; acc.x=wb[n]; acc.y=wb[n+1]; acc.z=wb[n+2]; acc.w=wb[n+3];
  #pragma unroll
  for (int t=0;t<3;t++){
    int ls = l-1+t; if (ls<0||ls>=128) continue;
    const float* cr = g_cc + ((b<<7)+ls)*64;
    #pragma unroll 4
    for (int i=0;i<64;i++){
      float v = cr[i];
      float4 wv = *(const float4*)(W + (size_t)(t*64+i)*512 + n);
      acc.x += v*wv.x; acc.y += v*wv.y; acc.z += v*wv.z; acc.w += v*wv.w;
    }
  }
  *(float4*)(g_bb + mrow*512 + n) = acc;
}

// ================= dilated conv (k=3, 64->64) — R9 scalar compute, float4 staging =====
#define DC_SMEM ((12288 + (128+2*27)*65 + 16)*4)
__global__ void __launch_bounds__(256) k_dilconv(int layer, int parity, int d,
                                                 const float* __restrict__ cw,
                                                 const float* __restrict__ cb){
  extern __shared__ float sm[];
  float* wS = sm;            // [t][i][o] 12288
  float* hS = sm + 12288;    // (128+2d) rows x pitch 65
  int b = blockIdx.y, n0 = blockIdx.x*128;
  int tid = threadIdx.x;
  const float* hb = g_h[parity] + (size_t)b*32768*64;
  const float* cwl = cw + (size_t)layer*3*64*64;
  // weights: contiguous float4 copy (12 LDG.128/thread)
  #pragma unroll 1
  for (int idx=tid; idx<3072; idx+=256)
    *(float4*)(wS + idx*4) = *(const float4*)(cwl + idx*4);
  // halo: float4 rows with per-row bounds
  int nrows = 128 + 2*d;
  #pragma unroll 1
  for (int idx=tid; idx<nrows*16; idx+=256){
    int rr = idx>>4, i4 = (idx&15)*4;
    int g = n0 - d + rr;
    float4 v = make_float4(0.f,0.f,0.f,0.f);
    if (g>=0 && g<32768) v = *(const float4*)(hb + (size_t)g*64 + i4);
    float* dst = hS + rr*65 + i4;
    dst[0]=leaky(v.x); dst[1]=leaky(v.y); dst[2]=leaky(v.z); dst[3]=leaky(v.w);
  }
  __syncthreads();
  int gch = tid&15, rg = tid>>4;
  int o4 = gch*4;
  int r0 = rg*8;
  float acc[4][8];
  #pragma unroll
  for (int cc2=0;cc2<4;cc2++)
    #pragma unroll
    for (int mm=0;mm<8;mm++) acc[cc2][mm]=0.f;
  #pragma unroll 1
  for (int i=0;i<64;i++){
    #pragma unroll
    for (int t=0;t<3;t++){
      float4 w = *(const float4*)(wS + t*4096 + i*64 + o4);
      const float* hrow = hS + (r0 + t*d)*65 + i;
      #pragma unroll
      for (int mm=0;mm<8;mm++){
        float a = hrow[mm*65];
        acc[0][mm] += a*w.x; acc[1][mm] += a*w.y;
        acc[2][mm] += a*w.z; acc[3][mm] += a*w.w;
      }
    }
  }
  float c0 = cb[layer*64 + o4], c1 = cb[layer*64 + o4+1];
  float c2 = cb[layer*64 + o4+2], c3 = cb[layer*64 + o4+3];
  float* ob = g_o1 + ((size_t)b*32768 + n0)*64;
  #pragma unroll
  for (int mm=0;mm<8;mm++){
    float4 v;
    v.x = leaky(acc[0][mm]+c0); v.y = leaky(acc[1][mm]+c1);
    v.z = leaky(acc[2][mm]+c2); v.w = leaky(acc[3][mm]+c3);
    *(float4*)(ob + (size_t)(r0+mm)*64 + o4) = v;
  }
}

// ================= LVC + gated residual — FFMA2 compute, float4 staging =========
#define LVC_SMEM ((16960 + 24576 + 128)*4)
__global__ void __launch_bounds__(512,1) k_lvc(int layer, int parity, int is_last,
                                               float* __restrict__ dout){
  extern __shared__ float sm[];
  float* seg = sm;                 // [i=64][pitch 265], m in [0,258)
  float* Ws  = sm + 16960;         // [k=192][64][2]
  float* bS  = sm + 16960 + 24576; // [128]
  int b = blockIdx.y, L = blockIdx.x;
  int tid = threadIdx.x;

  const float* o1b = g_o1 + (size_t)b*32768*64;
  int t0 = L*256 - 1;
  // seg: float4 along i, scatter to [i][m]
  #pragma unroll 1
  for (int idx=tid; idx<258*16; idx+=512){
    int m = idx>>4, i4 = (idx&15)*4;
    int t = t0 + m;
    float4 v = make_float4(0.f,0.f,0.f,0.f);
    if (t>=0 && t<32768) v = *(const float4*)(o1b + (size_t)t*64 + i4);
    seg[(i4+0)*265 + m] = v.x;
    seg[(i4+1)*265 + m] = v.y;
    seg[(i4+2)*265 + m] = v.z;
    seg[(i4+3)*265 + m] = v.w;
  }
  int la = layer*128 + L;
  int l = la>>2, q = la&3;
  const float* kb = g_k + (size_t)(b*128+l)*98304 + q*24576;
  // W: float4 loads, in-register de-interleave scatter
  #pragma unroll 1
  for (int idx=tid; idx<6144; idx+=512){
    float4 v = *(const float4*)(kb + idx*4);
    int base = idx*4;
    float vv[4] = {v.x, v.y, v.z, v.w};
    #pragma unroll
    for (int e=0;e<4;e++){
      int g = base + e;
      int i = g/384; int rem = g - i*384; int o = rem/3; int kk = rem - o*3;
      Ws[((i*3+kk)*64 + (o&63))*2 + (o>>6)] = vv[e];
    }
  }
  if (tid < 128) bS[tid] = g_bb[(b*128+l)*512 + q*128 + tid];
  __syncthreads();

  int ts = tid&31, to = tid>>5;   // to in [0,16)
  const float* hin = g_h[parity];
  float* hout = is_last ? dout : g_h[parity^1];
  size_t nbase = (size_t)b*32768 + (size_t)L*256;
  float b0 = bS[ts], b1 = bS[ts+64], b2 = bS[ts+32], b3 = bS[ts+96];

  #pragma unroll 1
  for (int ph=0; ph<2; ph++){
    int sbase = to*16 + ph*8;
    int mmidx[8][3];
    #pragma unroll
    for (int ss=0;ss<8;ss++)
      #pragma unroll
      for (int kk=0;kk<3;kk++){
        int pos = 3*(sbase+ss) + kk - 255;
        if (pos < 0) pos = -pos;
        else if (pos > 257) pos = 514 - pos;
        mmidx[ss][kk] = pos;
      }
    unsigned long long ac01[8], ac23[8];
    #pragma unroll
    for (int ss=0;ss<8;ss++){ ac01[ss]=0ULL; ac23[ss]=0ULL; }
    for (int i=0;i<64;i++){
      const float* segr = seg + i*265;
      #pragma unroll
      for (int kk=0;kk<3;kk++){
        const float* wr = Ws + (i*3+kk)*128;
        unsigned long long w01 = *(const unsigned long long*)(wr + 2*ts);
        unsigned long long w23 = *(const unsigned long long*)(wr + 2*ts + 64);
        #pragma unroll
        for (int ss=0;ss<8;ss++){
          unsigned long long ad = dup2(segr[mmidx[ss][kk]]);
          ffma2(ac01[ss], ad, w01);
          ffma2(ac23[ss], ad, w23);
        }
      }
    }
    #pragma unroll
    for (int ss=0;ss<8;ss++){
      size_t gi = (nbase + sbase + ss)*64;
      float2 p01 = unp2(ac01[ss]);
      float s0 = p01.x+b0, t1 = p01.y+b1;
      float g0 = (1.f/(1.f+__expf(-s0))) * tanhf(t1);
      hout[gi+ts] = hin[gi+ts] + g0;
      float2 p23 = unp2(ac23[ss]);
      float s2 = p23.x+b2, t3 = p23.y+b3;
      float g1 = (1.f/(1.f+__expf(-s2))) * tanhf(t3);
      hout[gi+ts+32] = hin[gi+ts+32] + g1;
    }
  }
}

// ================= launch =================
extern "C" void kernel_launch(void* const* d_in, const int* in_sizes, int n_in,
                              void* d_out, int out_size){
  const float* x      = (const float*)d_in[0];
  const float* c      = (const float*)d_in[1];
  const float* ct_w   = (const float*)d_in[2];
  const float* ct_b   = (const float*)d_in[3];
  const float* conv_w = (const float*)d_in[4];
  const float* conv_b = (const float*)d_in[5];
  const float* inp_w  = (const float*)d_in[6];
  const float* inp_b  = (const float*)d_in[7];
  const float* res_w1 = (const float*)d_in[8];
  const float* res_b1 = (const float*)d_in[9];
  const float* res_w2 = (const float*)d_in[10];
  const float* res_b2 = (const float*)d_in[11];
  const float* kern_w = (const float*)d_in[12];
  const float* kern_b = (const float*)d_in[13];
  const float* bias_w = (const float*)d_in[14];
  const float* bias_b = (const float*)d_in[15];
  float* out = (float*)d_out;

  cudaFuncSetAttribute(k_cond_fused, cudaFuncAttributeMaxDynamicSharedMemorySize, COND_SMEM);
  cudaFuncSetAttribute(k_gemm,    cudaFuncAttributeMaxDynamicSharedMemorySize, GEMM_SMEM);
  cudaFuncSetAttribute(k_dilconv, cudaFuncAttributeMaxDynamicSharedMemorySize, DC_SMEM);
  cudaFuncSetAttribute(k_lvc,     cudaFuncAttributeMaxDynamicSharedMemorySize, LVC_SMEM);
  cudaFuncSetAttribute(k_convt,   cudaFuncAttributeMaxDynamicSharedMemorySize, CT_SMEM);

  // 1: cond net -> g_cc
  k_cond_fused<<<dim3(8,4), 256, COND_SMEM>>>(c, inp_w, inp_b, res_w1, res_b1, res_w2, res_b2);
  // 2,3: conv_transpose -> g_h[0]
  k_convt<<<dim3(128,4), 256, CT_SMEM>>>(x, ct_w, ct_b);
  k_convt_edge<<<4, 256>>>(x, ct_w, ct_b);
  // 4: dilated conv layer 0  (<- 4th launch: ncu captures this)
  k_dilconv<<<dim3(256,4), 256, DC_SMEM>>>(0, 0, 1, conv_w, conv_b);
  // 5: kernel predictor GEMM
  k_gemm<<<dim3(768,8), 256, GEMM_SMEM>>>(kern_w, kern_b);
  // 6: bias predictor
  k_gemm_b<<<512, 128>>>(bias_w, bias_b);
  // 7: LVC layer 0
  k_lvc<<<dim3(128,4), 512, LVC_SMEM>>>(0, 0, 0, out);
  // layers 1-3
  const int dil[4] = {1,3,9,27};
  for (int a=1;a<4;a++){
    int parity = a & 1;
    k_dilconv<<<dim3(256,4), 256, DC_SMEM>>>(a, parity, dil[a], conv_w, conv_b);
    k_lvc<<<dim3(128,4), 512, LVC_SMEM>>>(a, parity, (a==3)?1:0, out);
  }
  (void)in_sizes; (void)n_in; (void)out_size;
}

// round 14
// speedup vs baseline: 2.2368x; 1.1728x over previous
#include <cuda_runtime.h>
#include <math.h>

#define DEVINL __device__ __forceinline__

static DEVINL float leaky(float v){ return v > 0.f ? v : 0.2f*v; }

// ---- packed f32x2 helpers (Blackwell FFMA2 path) ----
static DEVINL unsigned long long dup2(float x){
  unsigned long long r; asm("mov.b64 %0, {%1, %1};" : "=l"(r) : "f"(x)); return r;
}
static DEVINL void ffma2(unsigned long long &d, unsigned long long a, unsigned long long b){
  asm("fma.rn.f32x2 %0, %1, %2, %0;" : "+l"(d) : "l"(a), "l"(b));
}
static DEVINL float2 unp2(unsigned long long v){
  float2 f; asm("mov.b64 {%0, %1}, %2;" : "=f"(f.x), "=f"(f.y) : "l"(v)); return f;
}

// ---------------- persistent scratch (no runtime allocation) ----------------
__device__ float g_cc [4*128*64];
__device__ float g_bb [512*512];
__device__ float g_k  [512*98304];            // 201 MB kernel-predictor output
__device__ float g_h  [2][4*32768*64];        // ping-pong h
__device__ float g_o1 [4*32768*64];           // dilated-conv output

// ================= fused cond net =================
#define COND_SMEM ((32*80 + 28*64 + 28*64 + 12288)*4)
__global__ void __launch_bounds__(256) k_cond_fused(
    const float* __restrict__ c,
    const float* __restrict__ inp_w, const float* __restrict__ inp_b,
    const float* __restrict__ res_w1, const float* __restrict__ res_b1,
    const float* __restrict__ res_w2, const float* __restrict__ res_b2){
  extern __shared__ float sm[];
  float* sC = sm;
  float* sA = sm + 32*80;
  float* sB = sA + 28*64;
  float* sW = sB + 28*64;
  int b = blockIdx.y, p0 = blockIdx.x*16;
  int tid = threadIdx.x;
  int o = tid & 63, q = tid >> 6;

  #pragma unroll 1
  for (int idx=tid; idx<32*80; idx+=256){
    int cr = idx/80, ch = idx - cr*80;
    int g = p0 - 8 + cr;
    sC[idx] = (g>=0 && g<128) ? c[((size_t)b*128+g)*80 + ch] : 0.f;
  }
  __syncthreads();

  {
    float acc[7];
    #pragma unroll
    for (int k=0;k<7;k++) acc[k] = inp_b[o];
    #pragma unroll 1
    for (int t=0;t<5;t++){
      #pragma unroll 1
      for (int i=0;i<80;i++){
        float w = inp_w[(t*80+i)*64 + o];
        #pragma unroll
        for (int k=0;k<7;k++){
          int r = -6 + q*7 + k;
          acc[k] += sC[(r+t+6)*80 + i] * w;
        }
      }
    }
    #pragma unroll
    for (int k=0;k<7;k++){
      int r = -6 + q*7 + k;
      int g = p0 + r;
      sA[(r+6)*64 + o] = (g>=0 && g<128) ? leaky(acc[k]) : 0.f;
    }
  }

  #pragma unroll 1
  for (int s=0; s<6; s++){
    int j = s>>1, half = s&1;
    const float* w  = half ? (res_w2 + (size_t)j*3*64*64) : (res_w1 + (size_t)j*3*64*64);
    const float* bi = half ? (res_b2 + j*64) : (res_b1 + j*64);
    __syncthreads();
    #pragma unroll 1
    for (int idx=tid; idx<12288; idx+=256) sW[idx] = w[idx];
    __syncthreads();
    const float* src = half ? sB : sA;
    int lo = s-5, hi = 21-s;
    float acc[7];
    int rr[7];
    #pragma unroll
    for (int k=0;k<7;k++){ acc[k] = bi[o]; rr[k] = lo + q*7 + k; }
    #pragma unroll 1
    for (int t=0;t<3;t++){
      #pragma unroll 1
      for (int i=0;i<64;i++){
        float wv = sW[(t*64+i)*64 + o];
        #pragma unroll
        for (int k=0;k<7;k++){
          int r = rr[k];
          if (r < hi) acc[k] += src[(r+t+5)*64 + i] * wv;
        }
      }
    }
    #pragma unroll
    for (int k=0;k<7;k++){
      int r = rr[k];
      if (r < hi){
        int g = p0 + r;
        if (half){
          if (g>=0 && g<128) sA[(r+6)*64+o] += leaky(acc[k]);
        } else {
          sB[(r+6)*64+o] = (g>=0 && g<128) ? leaky(acc[k]) : 0.f;
        }
      }
    }
  }
  __syncthreads();

  #pragma unroll 1
  for (int idx=tid; idx<16*64; idx+=256){
    int r = idx>>6, oo = idx&63;
    g_cc[((size_t)b*128 + p0 + r)*64 + oo] = sA[(r+6)*64 + oo];
  }
}

// ================= conv_transpose (k=16, s=8, pad (11,11)) — FFMA2 =================
#define CT_SMEM ((2176 + 8192)*4)
__global__ void __launch_bounds__(256) k_convt(const float* __restrict__ x,
                                               const float* __restrict__ ctw,
                                               const float* __restrict__ ctb){
  extern __shared__ float sm[];
  float* lxS = sm;          // 33 rows x pitch 65
  float* wS  = sm + 2176;   // 16 taps x 8 i x 64 o (chunk)
  int b = blockIdx.y, m0 = blockIdx.x*32;
  int tid = threadIdx.x;
  const float* xb = x + (size_t)b*4096*64;
  #pragma unroll 1
  for (int idx=tid; idx<33*64; idx+=256){
    int rr=idx>>6, i=idx&63; int m=m0+rr;
    lxS[rr*65+i] = (m<4096) ? leaky(xb[(size_t)m*64+i]) : 0.f;
  }
  int ts=tid&31, to=tid>>5;
  unsigned long long acc2[4][8];
  #pragma unroll
  for (int mm=0;mm<4;mm++)
    #pragma unroll
    for (int j=0;j<8;j++) acc2[mm][j]=0ULL;

  for (int ch=0; ch<8; ch++){
    __syncthreads();
    #pragma unroll 1
    for (int idx=tid; idx<2048; idx+=256){
      int tap = idx>>7; int rem = idx&127; int ii=rem>>4; int o4=(rem&15)*4;
      *(float4*)(wS + tap*512 + ii*64 + o4) =
        *(const float4*)(ctw + (size_t)tap*4096 + (ch*8+ii)*64 + o4);
    }
    __syncthreads();
    #pragma unroll
    for (int ii=0;ii<8;ii++){
      unsigned long long lxd[5];
      #pragma unroll
      for (int r=0;r<5;r++) lxd[r] = dup2(lxS[(to*4+r)*65 + (ch*8+ii)]);
      #pragma unroll
      for (int tap=0;tap<8;tap++){
        unsigned long long w2 = *(const unsigned long long*)(wS + tap*512 + ii*64 + 2*ts);
        int j = 7-tap;
        #pragma unroll
        for (int mm=0;mm<4;mm++) ffma2(acc2[mm][j], lxd[mm], w2);
      }
      #pragma unroll
      for (int tap=8;tap<16;tap++){
        unsigned long long w2 = *(const unsigned long long*)(wS + tap*512 + ii*64 + 2*ts);
        int j = 15-tap;
        #pragma unroll
        for (int mm=0;mm<4;mm++) ffma2(acc2[mm][j], lxd[mm+1], w2);
      }
    }
  }
  float c0 = ctb[2*ts], c1 = ctb[2*ts+1];
  float* hb = g_h[0] + (size_t)b*32768*64;
  #pragma unroll
  for (int mm=0;mm<4;mm++)
    #pragma unroll
    for (int j=0;j<8;j++){
      int n = 8*(m0+to*4+mm)+4+j;
      if (n < 32768){
        float2 p = unp2(acc2[mm][j]);
        float2 v; v.x = p.x+c0; v.y = p.y+c1;
        *(float2*)(hb + (size_t)n*64 + 2*ts) = v;
      }
    }
}

// n = 0..3: single tap 11-n from x[0]
__global__ void k_convt_edge(const float* __restrict__ x, const float* __restrict__ ctw,
                             const float* __restrict__ ctb){
  int b = blockIdx.x; int n = threadIdx.x>>6, o = threadIdx.x&63;
  const float* xb = x + (size_t)b*4096*64;
  float acc = ctb[o];
  int tap = 11-n;
  #pragma unroll 8
  for (int i=0;i<64;i++) acc += leaky(xb[i]) * ctw[(size_t)tap*4096 + i*64 + o];
  g_h[0][((size_t)b*32768+n)*64+o] = acc;
}

// ========= kernel-predictor GEMM [512 x 98304] — FFMA2 (proven R9 version) =========
#define GEMM_SMEM ((12288 + 2048)*4)
__global__ void __launch_bounds__(256) k_gemm(const float* __restrict__ W,
                                              const float* __restrict__ wb){
  extern __shared__ float smg[];
  float* As = smg;          // [k=192][m=64]
  float* Bs = smg + 12288;  // 2 x [8][128]
  int tid = threadIdx.x;
  int n0 = blockIdx.x*128, m0 = blockIdx.y*64;
  #pragma unroll 1
  for (int it=0; it<48; it++){
    int idx = tid + it*256;
    int k = idx>>6, mm_ = idx&63;
    int mg = m0+mm_; int b2 = mg>>7, l = mg&127;
    int t = k>>6, ic = k&63, ls = l-1+t;
    As[idx] = (ls>=0 && ls<128) ? g_cc[((b2<<7)+ls)*64+ic] : 0.f;
  }
  int brow = tid>>5, bcol = (tid&31)*4;
  *(float4*)(Bs + brow*128 + bcol) = *(const float4*)(W + (size_t)brow*98304 + n0 + bcol);
  __syncthreads();
  int tn = tid&15, tm = tid>>4;
  unsigned long long acc2[4][4];
  #pragma unroll
  for (int r=0;r<4;r++)
    #pragma unroll
    for (int q=0;q<4;q++) acc2[r][q]=0ULL;
  for (int kc=0; kc<24; kc++){
    float4 nb;
    if (kc<23) nb = *(const float4*)(W + (size_t)((kc+1)*8+brow)*98304 + n0 + bcol);
    const float* Bc = Bs + (kc&1)*1024;
    #pragma unroll
    for (int kk=0; kk<8; kk++){
      int k = kc*8+kk;
      float4 a = *(const float4*)(As + k*64 + tm*4);
      ulonglong2 bA = *(const ulonglong2*)(Bc + kk*128 + tn*4);
      ulonglong2 bB = *(const ulonglong2*)(Bc + kk*128 + 64 + tn*4);
      unsigned long long ad[4];
      ad[0]=dup2(a.x); ad[1]=dup2(a.y); ad[2]=dup2(a.z); ad[3]=dup2(a.w);
      #pragma unroll
      for (int r=0;r<4;r++){
        ffma2(acc2[r][0], ad[r], bA.x);
        ffma2(acc2[r][1], ad[r], bA.y);
        ffma2(acc2[r][2], ad[r], bB.x);
        ffma2(acc2[r][3], ad[r], bB.y);
      }
    }
    __syncthreads();
    if (kc<23) *(float4*)(Bs + ((kc+1)&1)*1024 + brow*128 + bcol) = nb;
    __syncthreads();
  }
  int c1 = n0 + tn*4, c2 = n0 + 64 + tn*4;
  float bb0[8];
  #pragma unroll
  for (int q=0;q<4;q++){ bb0[q] = wb[c1+q]; bb0[q+4] = wb[c2+q]; }
  #pragma unroll
  for (int r=0;r<4;r++){
    size_t row = (size_t)(m0 + tm*4 + r)*98304;
    float2 p0 = unp2(acc2[r][0]), p1 = unp2(acc2[r][1]);
    float2 p2 = unp2(acc2[r][2]), p3 = unp2(acc2[r][3]);
    float4 v1, v2;
    v1.x=p0.x+bb0[0]; v1.y=p0.y+bb0[1]; v1.z=p1.x+bb0[2]; v1.w=p1.y+bb0[3];
    v2.x=p2.x+bb0[4]; v2.y=p2.y+bb0[5]; v2.z=p3.x+bb0[6]; v2.w=p3.y+bb0[7];
    *(float4*)(g_k + row + c1) = v1;
    *(float4*)(g_k + row + c2) = v2;
  }
}

// ================= bias-predictor GEMM: [512 x 512] =================
__global__ void k_gemm_b(const float* __restrict__ W, const float* __restrict__ wb){
  int mrow = blockIdx.x;
  int b = mrow>>7, l = mrow&127;
  int n = threadIdx.x*4;
  float4 acc; acc.x=wb[n]; acc.y=wb[n+1]; acc.z=wb[n+2]; acc.w=wb[n+3];
  #pragma unroll
  for (int t=0;t<3;t++){
    int ls = l-1+t; if (ls<0||ls>=128) continue;
    const float* cr = g_cc + ((b<<7)+ls)*64;
    #pragma unroll 4
    for (int i=0;i<64;i++){
      float v = cr[i];
      float4 wv = *(const float4*)(W + (size_t)(t*64+i)*512 + n);
      acc.x += v*wv.x; acc.y += v*wv.y; acc.z += v*wv.z; acc.w += v*wv.w;
    }
  }
  *(float4*)(g_bb + mrow*512 + n) = acc;
}

// ================= dilated conv (k=3, 64->64) — scalar compute, float4 staging =====
#define DC_SMEM ((12288 + (128+2*27)*65 + 16)*4)
__global__ void __launch_bounds__(256) k_dilconv(int layer, int parity, int d,
                                                 const float* __restrict__ cw,
                                                 const float* __restrict__ cb){
  extern __shared__ float sm[];
  float* wS = sm;            // [t][i][o] 12288
  float* hS = sm + 12288;    // (128+2d) rows x pitch 65
  int b = blockIdx.y, n0 = blockIdx.x*128;
  int tid = threadIdx.x;
  const float* hb = g_h[parity] + (size_t)b*32768*64;
  const float* cwl = cw + (size_t)layer*3*64*64;
  #pragma unroll 1
  for (int idx=tid; idx<3072; idx+=256)
    *(float4*)(wS + idx*4) = *(const float4*)(cwl + idx*4);
  int nrows = 128 + 2*d;
  #pragma unroll 1
  for (int idx=tid; idx<nrows*16; idx+=256){
    int rr = idx>>4, i4 = (idx&15)*4;
    int g = n0 - d + rr;
    float4 v = make_float4(0.f,0.f,0.f,0.f);
    if (g>=0 && g<32768) v = *(const float4*)(hb + (size_t)g*64 + i4);
    float* dst = hS + rr*65 + i4;
    dst[0]=leaky(v.x); dst[1]=leaky(v.y); dst[2]=leaky(v.z); dst[3]=leaky(v.w);
  }
  __syncthreads();
  int gch = tid&15, rg = tid>>4;
  int o4 = gch*4;
  int r0 = rg*8;
  float acc[4][8];
  #pragma unroll
  for (int cc2=0;cc2<4;cc2++)
    #pragma unroll
    for (int mm=0;mm<8;mm++) acc[cc2][mm]=0.f;
  #pragma unroll 1
  for (int i=0;i<64;i++){
    #pragma unroll
    for (int t=0;t<3;t++){
      float4 w = *(const float4*)(wS + t*4096 + i*64 + o4);
      const float* hrow = hS + (r0 + t*d)*65 + i;
      #pragma unroll
      for (int mm=0;mm<8;mm++){
        float a = hrow[mm*65];
        acc[0][mm] += a*w.x; acc[1][mm] += a*w.y;
        acc[2][mm] += a*w.z; acc[3][mm] += a*w.w;
      }
    }
  }
  float c0 = cb[layer*64 + o4], c1 = cb[layer*64 + o4+1];
  float c2 = cb[layer*64 + o4+2], c3 = cb[layer*64 + o4+3];
  float* ob = g_o1 + ((size_t)b*32768 + n0)*64;
  #pragma unroll
  for (int mm=0;mm<8;mm++){
    float4 v;
    v.x = leaky(acc[0][mm]+c0); v.y = leaky(acc[1][mm]+c1);
    v.z = leaky(acc[2][mm]+c2); v.w = leaky(acc[3][mm]+c3);
    *(float4*)(ob + (size_t)(r0+mm)*64 + o4) = v;
  }
}

// ================= LVC + gated residual — GEMM-tiled, lanes = distinct s =========
// seg [m=0..257][i=0..63] pitch 68 (float4-aligned staging, conflict-free lane reads)
// Ws  [k=0..191] row pitch 160; o-group og (8 groups of 8 o) at og*20; pair (o, o+64)
//     at og*20 + (o&7)*2 + (o>>6).  Bank-staggered: starts 0,20,8,28,16,4,24,12.
#define SEG_PITCH 68
#define SEG_FLOATS (258*SEG_PITCH)
#define WS_PITCH 160
#define LVC_SMEM ((SEG_FLOATS + 192*WS_PITCH + 128)*4)
__global__ void __launch_bounds__(512,1) k_lvc(int layer, int parity, int is_last,
                                               float* __restrict__ dout){
  extern __shared__ float sm[];
  float* seg = sm;                       // SEG_FLOATS
  float* Ws  = sm + SEG_FLOATS;          // 192*160
  float* bS  = Ws + 192*WS_PITCH;        // [128]
  int b = blockIdx.y, L = blockIdx.x;
  int tid = threadIdx.x;

  const float* o1b = g_o1 + (size_t)b*32768*64;
  int t0 = L*256 - 1;
  // seg staging: identity float4 copy into [m][i]
  #pragma unroll 1
  for (int idx=tid; idx<258*16; idx+=512){
    int m = idx>>4, i4 = (idx&15)*4;
    int t = t0 + m;
    float4 v = make_float4(0.f,0.f,0.f,0.f);
    if (t>=0 && t<32768) v = *(const float4*)(o1b + (size_t)t*64 + i4);
    *(float4*)(seg + m*SEG_PITCH + i4) = v;
  }
  int la = layer*128 + L;
  int l = la>>2, q = la&3;
  const float* kb = g_k + (size_t)(b*128+l)*98304 + q*24576;
  // W staging: float4 loads, scatter to bank-staggered pair layout
  #pragma unroll 1
  for (int idx=tid; idx<6144; idx+=512){
    float4 v = *(const float4*)(kb + idx*4);
    int base = idx*4;
    float vv[4] = {v.x, v.y, v.z, v.w};
    #pragma unroll
    for (int e=0;e<4;e++){
      int g = base + e;
      int i = g/384; int rem = g - i*384; int o = rem/3; int kk = rem - o*3;
      int col = o & 63, half = o >> 6;
      Ws[(i*3+kk)*WS_PITCH + (col>>3)*20 + (col&7)*2 + half] = vv[e];
    }
  }
  if (tid < 128) bS[tid] = g_bb[(b*128+l)*512 + q*128 + tid];
  __syncthreads();

  int og = tid & 7;        // o-group: channels o0..o0+7
  int sgl = tid >> 3;      // 0..63: s values sgl + r*64
  int o0 = og*8;

  // patch position addresses (pos*SEG_PITCH), 4 s x 3 kk
  int addr[4][3];
  #pragma unroll
  for (int r=0;r<4;r++)
    #pragma unroll
    for (int kk=0;kk<3;kk++){
      int s = r*64 + sgl;
      int pos = 3*s + kk - 255;
      if (pos < 0) pos = -pos;
      else if (pos > 257) pos = 514 - pos;
      addr[r][kk] = pos*SEG_PITCH;
    }

  unsigned long long acc[4][8];
  #pragma unroll
  for (int r=0;r<4;r++)
    #pragma unroll
    for (int j=0;j<8;j++) acc[r][j]=0ULL;

  #pragma unroll 1
  for (int i=0;i<64;i++){
    #pragma unroll
    for (int kk=0;kk<3;kk++){
      const float* wr = Ws + (i*3+kk)*WS_PITCH + og*20;
      ulonglong2 wA = *(const ulonglong2*)(wr);
      ulonglong2 wB = *(const ulonglong2*)(wr+4);
      ulonglong2 wC = *(const ulonglong2*)(wr+8);
      ulonglong2 wD = *(const ulonglong2*)(wr+12);
      #pragma unroll
      for (int r=0;r<4;r++){
        unsigned long long ad = dup2(seg[addr[r][kk] + i]);
        ffma2(acc[r][0], ad, wA.x); ffma2(acc[r][1], ad, wA.y);
        ffma2(acc[r][2], ad, wB.x); ffma2(acc[r][3], ad, wB.y);
        ffma2(acc[r][4], ad, wC.x); ffma2(acc[r][5], ad, wC.y);
        ffma2(acc[r][6], ad, wD.x); ffma2(acc[r][7], ad, wD.y);
      }
    }
  }

  const float* hin = g_h[parity];
  float* hout = is_last ? dout : g_h[parity^1];
  size_t nbase = (size_t)b*32768 + (size_t)L*256;
  float4 bl0 = *(const float4*)(bS + o0);
  float4 bl1 = *(const float4*)(bS + o0 + 4);
  float4 bh0 = *(const float4*)(bS + o0 + 64);
  float4 bh1 = *(const float4*)(bS + o0 + 68);
  float blo[8] = {bl0.x,bl0.y,bl0.z,bl0.w, bl1.x,bl1.y,bl1.z,bl1.w};
  float bhi[8] = {bh0.x,bh0.y,bh0.z,bh0.w, bh1.x,bh1.y,bh1.z,bh1.w};

  #pragma unroll
  for (int r=0;r<4;r++){
    int s = r*64 + sgl;
    size_t gi = (nbase + s)*64 + o0;
    float4 h0 = *(const float4*)(hin + gi);
    float4 h1 = *(const float4*)(hin + gi + 4);
    float hv[8] = {h0.x,h0.y,h0.z,h0.w, h1.x,h1.y,h1.z,h1.w};
    float ov[8];
    #pragma unroll
    for (int j=0;j<8;j++){
      float2 p = unp2(acc[r][j]);
      float sg = 1.f/(1.f+__expf(-(p.x + blo[j])));
      float th = tanhf(p.y + bhi[j]);
      ov[j] = hv[j] + sg*th;
    }
    float4 v0 = make_float4(ov[0],ov[1],ov[2],ov[3]);
    float4 v1 = make_float4(ov[4],ov[5],ov[6],ov[7]);
    *(float4*)(hout + gi) = v0;
    *(float4*)(hout + gi + 4) = v1;
  }
}

// ================= launch =================
extern "C" void kernel_launch(void* const* d_in, const int* in_sizes, int n_in,
                              void* d_out, int out_size){
  const float* x      = (const float*)d_in[0];
  const float* c      = (const float*)d_in[1];
  const float* ct_w   = (const float*)d_in[2];
  const float* ct_b   = (const float*)d_in[3];
  const float* conv_w = (const float*)d_in[4];
  const float* conv_b = (const float*)d_in[5];
  const float* inp_w  = (const float*)d_in[6];
  const float* inp_b  = (const float*)d_in[7];
  const float* res_w1 = (const float*)d_in[8];
  const float* res_b1 = (const float*)d_in[9];
  const float* res_w2 = (const float*)d_in[10];
  const float* res_b2 = (const float*)d_in[11];
  const float* kern_w = (const float*)d_in[12];
  const float* kern_b = (const float*)d_in[13];
  const float* bias_w = (const float*)d_in[14];
  const float* bias_b = (const float*)d_in[15];
  float* out = (float*)d_out;

  cudaFuncSetAttribute(k_cond_fused, cudaFuncAttributeMaxDynamicSharedMemorySize, COND_SMEM);
  cudaFuncSetAttribute(k_gemm,    cudaFuncAttributeMaxDynamicSharedMemorySize, GEMM_SMEM);
  cudaFuncSetAttribute(k_dilconv, cudaFuncAttributeMaxDynamicSharedMemorySize, DC_SMEM);
  cudaFuncSetAttribute(k_lvc,     cudaFuncAttributeMaxDynamicSharedMemorySize, LVC_SMEM);
  cudaFuncSetAttribute(k_convt,   cudaFuncAttributeMaxDynamicSharedMemorySize, CT_SMEM);

  // 1: cond net -> g_cc
  k_cond_fused<<<dim3(8,4), 256, COND_SMEM>>>(c, inp_w, inp_b, res_w1, res_b1, res_w2, res_b2);
  // 2,3: conv_transpose -> g_h[0]
  k_convt<<<dim3(128,4), 256, CT_SMEM>>>(x, ct_w, ct_b);
  k_convt_edge<<<4, 256>>>(x, ct_w, ct_b);
  // 4: dilated conv layer 0  (<- 4th launch: ncu captures this)
  k_dilconv<<<dim3(256,4), 256, DC_SMEM>>>(0, 0, 1, conv_w, conv_b);
  // 5: kernel predictor GEMM
  k_gemm<<<dim3(768,8), 256, GEMM_SMEM>>>(kern_w, kern_b);
  // 6: bias predictor
  k_gemm_b<<<512, 128>>>(bias_w, bias_b);
  // 7: LVC layer 0
  k_lvc<<<dim3(128,4), 512, LVC_SMEM>>>(0, 0, 0, out);
  // layers 1-3
  const int dil[4] = {1,3,9,27};
  for (int a=1;a<4;a++){
    int parity = a & 1;
    k_dilconv<<<dim3(256,4), 256, DC_SMEM>>>(a, parity, dil[a], conv_w, conv_b);
    k_lvc<<<dim3(128,4), 512, LVC_SMEM>>>(a, parity, (a==3)?1:0, out);
  }
  (void)in_sizes; (void)n_in; (void)out_size;
}